// round 6
// baseline (speedup 1.0000x reference)
#include <cuda_runtime.h>
#include <cuda_bf16.h>

// z:     [M=4096, P=2]  float32
// mu:    [B=8, N=2048, P=2] float32
// sigma: [B=8, N=2048, 1] float32
// out:   [B, N, M] float32 = exp(-d2 / (2*sig^2)), sig = clip(sigma, 0.1, 10)
//
// One block of 256 threads per (b,n) row; each thread produces 16 consecutive
// m-values via 4 STG.128. exp(x) computed as exp2(x * log2(e)) -> MUFU.EX2.

#define M_GRID 4096
#define THREADS 256
#define M_PER_THREAD 16   // 4 x float4

__global__ void __launch_bounds__(THREADS) rbf_kernel(
    const float* __restrict__ z,
    const float* __restrict__ mu,
    const float* __restrict__ sigma,
    float* __restrict__ out)
{
    const int row = blockIdx.x;            // b*N + n
    const int t   = threadIdx.x;

    // Per-row constants (broadcast loads within the block)
    const float mu0 = __ldg(&mu[row * 2 + 0]);
    const float mu1 = __ldg(&mu[row * 2 + 1]);
    float s = __ldg(&sigma[row]);
    s = fminf(fmaxf(s, 0.1f), 10.0f);
    // exp(-d2/(2 s^2)) = exp2(d2 * c),  c = -log2(e) / (2 s^2)
    const float c = -1.44269504088896340736f / (2.0f * s * s);

    // This thread's 16 m-values: m0 = t*16 .. t*16+15
    // z floats for those: indices [2*m0, 2*m0+32) -> 8 float4 loads
    const float4* zv = reinterpret_cast<const float4*>(z) + (size_t)t * 8;
    float4* ov = reinterpret_cast<float4*>(out + (size_t)row * M_GRID) + (size_t)t * 4;

    #pragma unroll
    for (int i = 0; i < 4; i++) {
        const float4 za = zv[2 * i];       // m+0, m+1 (x,y / z,w)
        const float4 zb = zv[2 * i + 1];   // m+2, m+3
        float4 o;
        float dx, dy;
        dx = za.x - mu0; dy = za.y - mu1; o.x = exp2f((dx * dx + dy * dy) * c);
        dx = za.z - mu0; dy = za.w - mu1; o.y = exp2f((dx * dx + dy * dy) * c);
        dx = zb.x - mu0; dy = zb.y - mu1; o.z = exp2f((dx * dx + dy * dy) * c);
        dx = zb.z - mu0; dy = zb.w - mu1; o.w = exp2f((dx * dx + dy * dy) * c);
        ov[i] = o;
    }
}

extern "C" void kernel_launch(void* const* d_in, const int* in_sizes, int n_in,
                              void* d_out, int out_size)
{
    const float* z     = (const float*)d_in[0];  // [4096, 2]
    const float* mu    = (const float*)d_in[1];  // [8, 2048, 2]
    const float* sigma = (const float*)d_in[2];  // [8, 2048, 1]
    float* out = (float*)d_out;                  // [8, 2048, 4096]

    const int rows = in_sizes[2];                // B*N = 16384
    rbf_kernel<<<rows, THREADS>>>(z, mu, sigma, out);
}

// round 7
// speedup vs baseline: 1.9445x; 1.9445x over previous
#include <cuda_runtime.h>
#include <cuda_bf16.h>

// z:     [M=4096, P=2]  float32   (32 KB, constant across rows -> registers)
// mu:    [B=8, N=2048, P=2] float32
// sigma: [B=8, N=2048, 1] float32
// out:   [B, N, M] float32 = exp(-d2 / (2*sig^2)), sig = clip(sigma, 0.1, 10)
//
// Persistent blocks: each thread loads its 16 z-points (32 floats) into
// registers ONCE, then grid-strides over (b,n) rows. Per row: 3 broadcast
// loads + 16 MUFU.EX2 + 4 streaming STG.128. This removes the redundant
// per-row z reloads that made the previous kernel L1tex-bound (L1=86%).

#define M_GRID  4096
#define THREADS 256
#define BLOCKS_PER_SM 4

__global__ void __launch_bounds__(THREADS, BLOCKS_PER_SM) rbf_kernel(
    const float* __restrict__ z,
    const float* __restrict__ mu,
    const float* __restrict__ sigma,
    float* __restrict__ out,
    int rows)
{
    const int t = threadIdx.x;

    // Load this thread's 16 (z0,z1) pairs once: z floats [32*t, 32*t+32)
    const float4* zv = reinterpret_cast<const float4*>(z) + (size_t)t * 8;
    float4 zr[8];
    #pragma unroll
    for (int i = 0; i < 8; i++) zr[i] = zv[i];

    for (int row = blockIdx.x; row < rows; row += gridDim.x) {
        const float mu0 = __ldg(&mu[row * 2 + 0]);
        const float mu1 = __ldg(&mu[row * 2 + 1]);
        float s = __ldg(&sigma[row]);
        s = fminf(fmaxf(s, 0.1f), 10.0f);
        // exp(-d2/(2 s^2)) = exp2(d2 * c),  c = -log2(e) / (2 s^2)
        const float c = -1.44269504088896340736f / (2.0f * s * s);

        float4* ov = reinterpret_cast<float4*>(out + (size_t)row * M_GRID)
                     + (size_t)t * 4;

        #pragma unroll
        for (int i = 0; i < 4; i++) {
            const float4 za = zr[2 * i];       // m+0, m+1
            const float4 zb = zr[2 * i + 1];   // m+2, m+3
            float4 o;
            float dx, dy;
            dx = za.x - mu0; dy = za.y - mu1; o.x = exp2f((dx * dx + dy * dy) * c);
            dx = za.z - mu0; dy = za.w - mu1; o.y = exp2f((dx * dx + dy * dy) * c);
            dx = zb.x - mu0; dy = zb.y - mu1; o.z = exp2f((dx * dx + dy * dy) * c);
            dx = zb.z - mu0; dy = zb.w - mu1; o.w = exp2f((dx * dx + dy * dy) * c);
            __stcs(&ov[i], o);                 // streaming store: never re-read
        }
    }
}

extern "C" void kernel_launch(void* const* d_in, const int* in_sizes, int n_in,
                              void* d_out, int out_size)
{
    const float* z     = (const float*)d_in[0];  // [4096, 2]
    const float* mu    = (const float*)d_in[1];  // [8, 2048, 2]
    const float* sigma = (const float*)d_in[2];  // [8, 2048, 1]
    float* out = (float*)d_out;                  // [8, 2048, 4096]

    const int rows = in_sizes[2];                // B*N = 16384
    int blocks = 148 * BLOCKS_PER_SM;            // persistent: 4 blocks/SM
    if (blocks > rows) blocks = rows;
    rbf_kernel<<<blocks, THREADS>>>(z, mu, sigma, out, rows);
}

// round 8
// speedup vs baseline: 2.0395x; 1.0489x over previous
#include <cuda_runtime.h>
#include <cuda_bf16.h>

// z:     [M=4096, P=2]  float32
// mu:    [B=8, N=2048, P=2] float32
// sigma: [B=8, N=2048, 1] float32
// out:   [B, N, M] float32 = exp(-d2 / (2*sig^2)), sig = clip(sigma, 0.1, 10)
//
// Persistent blocks; each block owns a fixed half-row (2048 m) so each thread
// keeps 8 z-points (zx, zy, zsq = 24 regs) resident forever. Rows are
// processed with the decomposed form:
//   arg = c*zsq + A*zx + B*zy + D,  A=-2c*mu0, B=-2c*mu1, D=c*(mu0^2+mu1^2)
// => 3 FFMA + 1 MUFU.EX2 per element (vs 5+1 before).
// Next row's mu/sigma are prefetched to hide the L2 broadcast-load latency.

#define M_GRID  4096
#define THREADS 256
#define BLOCKS_PER_SM 5
#define M_PER_THREAD 8

__global__ void __launch_bounds__(THREADS, BLOCKS_PER_SM) rbf_kernel(
    const float* __restrict__ z,
    const float* __restrict__ mu,
    const float* __restrict__ sigma,
    float* __restrict__ out,
    int rows)
{
    const int t    = threadIdx.x;
    const int half = blockIdx.x & 1;            // which 2048-wide half of the row
    const int rstart  = blockIdx.x >> 1;
    const int rstride = gridDim.x >> 1;

    // This thread's 8 m-values: m0 = half*2048 + t*8
    const int m0 = half * (M_GRID / 2) + t * M_PER_THREAD;

    // Load z once: floats [2*m0, 2*m0+16) = 4 float4
    float zx[M_PER_THREAD], zy[M_PER_THREAD], zsq[M_PER_THREAD];
    {
        const float4* zv = reinterpret_cast<const float4*>(z + 2 * m0);
        #pragma unroll
        for (int i = 0; i < 4; i++) {
            float4 v = zv[i];
            zx[2*i]   = v.x; zy[2*i]   = v.y;
            zx[2*i+1] = v.z; zy[2*i+1] = v.w;
        }
        #pragma unroll
        for (int i = 0; i < M_PER_THREAD; i++)
            zsq[i] = zx[i] * zx[i] + zy[i] * zy[i];
    }

    // Prefetch first row's params
    float mu0 = __ldg(&mu[rstart * 2 + 0]);
    float mu1 = __ldg(&mu[rstart * 2 + 1]);
    float sg  = __ldg(&sigma[rstart]);

    for (int row = rstart; row < rows; row += rstride) {
        // Consume current params
        const float m0v = mu0, m1v = mu1;
        float s = fminf(fmaxf(sg, 0.1f), 10.0f);

        // Prefetch next row's params (overlaps with compute below)
        const int nrow = row + rstride;
        if (nrow < rows) {
            mu0 = __ldg(&mu[nrow * 2 + 0]);
            mu1 = __ldg(&mu[nrow * 2 + 1]);
            sg  = __ldg(&sigma[nrow]);
        }

        const float c = -1.44269504088896340736f / (2.0f * s * s);
        const float A = -2.0f * c * m0v;
        const float B = -2.0f * c * m1v;
        const float D = c * (m0v * m0v + m1v * m1v);

        float r[M_PER_THREAD];
        #pragma unroll
        for (int i = 0; i < M_PER_THREAD; i++) {
            float e = fmaf(zy[i], B, D);
            e = fmaf(zx[i], A, e);
            e = fmaf(zsq[i], c, e);
            r[i] = exp2f(e);
        }

        float4* ov = reinterpret_cast<float4*>(out + (size_t)row * M_GRID + m0);
        __stcs(&ov[0], make_float4(r[0], r[1], r[2], r[3]));
        __stcs(&ov[1], make_float4(r[4], r[5], r[6], r[7]));
    }
}

extern "C" void kernel_launch(void* const* d_in, const int* in_sizes, int n_in,
                              void* d_out, int out_size)
{
    const float* z     = (const float*)d_in[0];  // [4096, 2]
    const float* mu    = (const float*)d_in[1];  // [8, 2048, 2]
    const float* sigma = (const float*)d_in[2];  // [8, 2048, 1]
    float* out = (float*)d_out;                  // [8, 2048, 4096]

    const int rows = in_sizes[2];                // B*N = 16384
    int blocks = 148 * BLOCKS_PER_SM * 2 / 2;    // 740, even (half split)
    blocks &= ~1;
    rbf_kernel<<<blocks, THREADS>>>(z, mu, sigma, out, rows);
}